// round 8
// baseline (speedup 1.0000x reference)
#include <cuda_runtime.h>
#include <math.h>

#define NNODES 50000
#define NEDGES 800000
#define NGRAPHS 64
#define NLOCS 50

// ---------------- device scratch ----------------
__device__ float g_h[(size_t)NNODES * 144];    // GEMM out (features + es + ed)
__device__ float g_act[(size_t)NNODES * 132];  // gather out / next GEMM in
__device__ float g_Wp0[8 * 144];
__device__ float g_Wp1[132 * 144];
__device__ float g_Wp2[132 * 132];
__device__ int g_deg[NNODES];
__device__ int g_cur[NNODES];
__device__ int g_rowptr[NNODES + 1];
__device__ int g_col[NEDGES];
__device__ float g_pool[NGRAPHS * 128];
__device__ int g_cnt[NGRAPHS];
// decoupled-lookback scan state
__device__ volatile int g_scanA[64];
__device__ volatile int g_scanP[64];
__device__ volatile int g_scanF[64];

__device__ __forceinline__ float leakyf(float v) { return v > 0.f ? v : 0.2f * v; }

// ---------------- fused setup: zero aux + pack all weights ----------------
// es[n,h] = sum_o h[n,h*O+o]*as[h,o] ==> fold attention dots into GEMM as extra columns.
__device__ __forceinline__ void pack_one(const float* __restrict__ W, const float* __restrict__ avs,
                                         const float* __restrict__ avd, float* __restrict__ Wp,
                                         int i, int K, int M, int MP, int H, int O, int ES, int ED) {
    int k = i / MP, j = i % MP;
    float v = 0.f;
    if (k < K) {
        if (j < M) {
            v = W[k * M + j];
        } else if (j >= ES && j < ES + H) {
            int h = j - ES; float s = 0.f;
            for (int o = 0; o < O; o++) s += W[k * M + h * O + o] * avs[h * O + o];
            v = s;
        } else if (j >= ED && j < ED + H) {
            int h = j - ED; float s = 0.f;
            for (int o = 0; o < O; o++) s += W[k * M + h * O + o] * avd[h * O + o];
            v = s;
        }
    }
    Wp[i] = v;
}

__global__ void setup_kernel(const float* __restrict__ W0, const float* __restrict__ as0,
                             const float* __restrict__ ad0, const float* __restrict__ W1,
                             const float* __restrict__ as1, const float* __restrict__ ad1,
                             const float* __restrict__ W2, const float* __restrict__ as2,
                             const float* __restrict__ ad2) {
    int b = blockIdx.x, t = threadIdx.x;
    if (b < 196) {  // zero aux
        int i = b * 256 + t;
        if (i < NNODES) { g_deg[i] = 0; g_cur[i] = 0; }
        if (i < NGRAPHS * 128) g_pool[i] = 0.f;
        if (i < NGRAPHS) g_cnt[i] = 0;
        if (i < 64) g_scanF[i] = 0;
    } else if (b < 201) {  // pack0: 8*144 = 1152
        int i = (b - 196) * 256 + t;
        if (i < 8 * 144) pack_one(W0, as0, ad0, g_Wp0, i, 6, 129, 144, 3, 43, 132, 136);
    } else if (b < 276) {  // pack1: 132*144 = 19008
        int i = (b - 201) * 256 + t;
        if (i < 132 * 144) pack_one(W1, as1, ad1, g_Wp1, i, 129, 129, 144, 3, 43, 132, 136);
    } else {  // pack2: 132*132 = 17424 (b in [276, 345))
        int i = (b - 276) * 256 + t;
        if (i < 132 * 132) pack_one(W2, as2, ad2, g_Wp2, i, 129, 128, 132, 1, 128, 128, 129);
    }
}

// ---------------- CSR build ----------------
__global__ void hist_kernel(const int* __restrict__ dstv) {
    int i = blockIdx.x * blockDim.x + threadIdx.x;
    if (i < NEDGES) atomicAdd(&g_deg[dstv[i]], 1);
}

// single-kernel exclusive scan via decoupled lookback (49 blocks, all co-resident)
__global__ void scan_lookback() {
    __shared__ int buf[1024];
    __shared__ int s_prev;
    int b = blockIdx.x, t = threadIdx.x;
    int idx = b * 1024 + t;
    int v = (idx < NNODES) ? g_deg[idx] : 0;
    buf[t] = v;
    __syncthreads();
    for (int off = 1; off < 1024; off <<= 1) {
        int a = (t >= off) ? buf[t - off] : 0;
        __syncthreads();
        buf[t] += a;
        __syncthreads();
    }
    if (t == 0) {
        int total = buf[1023];
        int run = 0;
        if (b == 0) {
            g_scanP[0] = total;
            __threadfence();
            g_scanF[0] = 2;
        } else {
            g_scanA[b] = total;
            __threadfence();
            g_scanF[b] = 1;
            int i = b - 1;
            while (i >= 0) {
                int f;
                while ((f = g_scanF[i]) == 0) {}
                if (f == 2) { run += g_scanP[i]; break; }
                run += g_scanA[i];
                i--;
            }
            g_scanP[b] = run + total;
            __threadfence();
            g_scanF[b] = 2;
        }
        s_prev = run;
    }
    __syncthreads();
    if (idx < NNODES) g_rowptr[idx + 1] = s_prev + buf[t];
    if (idx == 0) g_rowptr[0] = 0;
}

__global__ void fill_kernel(const int* __restrict__ srcv, const int* __restrict__ dstv) {
    int i = blockIdx.x * blockDim.x + threadIdx.x;
    if (i < NEDGES) {
        int d = dstv[i];
        int p = atomicAdd(&g_cur[d], 1);
        g_col[g_rowptr[d] + p] = srcv[i];
    }
}

// ---------------- layer-0 GEMM (K=6) ----------------
__global__ void gemm0_kernel(const float* __restrict__ x) {
    int n = blockIdx.x;
    int j = threadIdx.x;
    float xr[6];
#pragma unroll
    for (int k = 0; k < 6; k++) xr[k] = __ldg(&x[n * 6 + k]);
    if (j < 144) {
        float a = 0.f;
#pragma unroll
        for (int k = 0; k < 6; k++) a += xr[k] * g_Wp0[k * 144 + j];
        g_h[(size_t)n * 144 + j] = a;
    }
}

// ---------------- tiled GEMM: g_act[N,132] @ Wp[132,MP] -> g_h[N,MP] ----------------
template <int MP>
__global__ void gemm_tiled(int wsel, int N) {
    constexpr int KP = 132;
    constexpr int TXN = MP / 4;
    constexpr int NTH = TXN * 8;
    __shared__ float xs[KP][68];  // transposed A tile
    const float* Wp = (wsel == 1) ? g_Wp1 : g_Wp2;
    const float4* W4 = (const float4*)Wp;
    int tx = threadIdx.x, ty = threadIdx.y;
    int t = ty * TXN + tx;
    int n0 = blockIdx.x * 64;
    for (int i = t; i < 64 * 33; i += NTH) {
        int n = i / 33, k4 = i % 33;
        int gn = n0 + n;
        float4 v = make_float4(0.f, 0.f, 0.f, 0.f);
        if (gn < N) v = __ldg((const float4*)(g_act + (size_t)gn * 132 + k4 * 4));
        xs[k4 * 4 + 0][n] = v.x;
        xs[k4 * 4 + 1][n] = v.y;
        xs[k4 * 4 + 2][n] = v.z;
        xs[k4 * 4 + 3][n] = v.w;
    }
    __syncthreads();
    float acc[8][4];
#pragma unroll
    for (int r = 0; r < 8; r++)
#pragma unroll
        for (int c = 0; c < 4; c++) acc[r][c] = 0.f;
    int nb = ty * 8;
#pragma unroll 4
    for (int k = 0; k < KP; k++) {
        float4 w = __ldg(&W4[k * TXN + tx]);
        float4 xa = *(const float4*)&xs[k][nb];
        float4 xb = *(const float4*)&xs[k][nb + 4];
        float xv[8] = {xa.x, xa.y, xa.z, xa.w, xb.x, xb.y, xb.z, xb.w};
#pragma unroll
        for (int r = 0; r < 8; r++) {
            acc[r][0] += xv[r] * w.x;
            acc[r][1] += xv[r] * w.y;
            acc[r][2] += xv[r] * w.z;
            acc[r][3] += xv[r] * w.w;
        }
    }
#pragma unroll
    for (int r = 0; r < 8; r++) {
        int gn = n0 + nb + r;
        if (gn < N) {
            float4 o = make_float4(acc[r][0], acc[r][1], acc[r][2], acc[r][3]);
            *(float4*)(g_h + (size_t)gn * MP + tx * 4) = o;
        }
    }
}

// ---------------- GAT gather: warp per dst node, CSR in-edges + implicit self-loop ----------------
// pass1: segment max; pass2: exp-weighted accumulate with deep software pipeline
// (col resolved 2 edges ahead, es/ed float4 issued 1 full iteration before use).
template <int H, int O, int M, int SIN, int ESOFF, int EDOFF, int SOUT, int ACT>
__global__ void gather_kernel(const float* __restrict__ bias) {
    int gw = (blockIdx.x * blockDim.x + threadIdx.x) >> 5;
    int lane = threadIdx.x & 31;
    if (gw >= NNODES) return;
    int n = gw;
    const float* hn = g_h + (size_t)n * SIN;
    float edv0 = __ldg(&hn[EDOFF]), edv1 = 0.f, edv2 = 0.f;
    float es0 = __ldg(&hn[ESOFF]), es1 = 0.f, es2 = 0.f;
    if (H > 1) { edv1 = __ldg(&hn[EDOFF + 1]); es1 = __ldg(&hn[ESOFF + 1]); }
    if (H > 2) { edv2 = __ldg(&hn[EDOFF + 2]); es2 = __ldg(&hn[ESOFF + 2]); }
    float se0 = leakyf(es0 + edv0), se1 = leakyf(es1 + edv1), se2 = leakyf(es2 + edv2);
    float mx0 = se0, mx1 = se1, mx2 = se2;
    int beg = __ldg(&g_rowptr[n]);
    int end = __ldg(&g_rowptr[n + 1]);
    // pass 1: segment max (lanes parallel over edges)
    for (int e = beg + lane; e < end; e += 32) {
        int s = __ldg(&g_col[e]);
        float4 eq = __ldg((const float4*)(g_h + (size_t)s * SIN + ESOFF));
        mx0 = fmaxf(mx0, leakyf(eq.x + edv0));
        if (H > 1) mx1 = fmaxf(mx1, leakyf(eq.y + edv1));
        if (H > 2) mx2 = fmaxf(mx2, leakyf(eq.z + edv2));
    }
#pragma unroll
    for (int o = 16; o > 0; o >>= 1) {
        mx0 = fmaxf(mx0, __shfl_xor_sync(0xffffffffu, mx0, o));
        if (H > 1) mx1 = fmaxf(mx1, __shfl_xor_sync(0xffffffffu, mx1, o));
        if (H > 2) mx2 = fmaxf(mx2, __shfl_xor_sync(0xffffffffu, mx2, o));
    }
    // self-loop contribution
    float wse0 = __expf(se0 - mx0);
    float wse1 = (H > 1) ? __expf(se1 - mx1) : 0.f;
    float wse2 = (H > 2) ? __expf(se2 - mx2) : 0.f;
    float z0 = wse0, z1 = wse1, z2 = wse2;
    constexpr int NI = (M + 31) / 32;
    int hsel[NI];
#pragma unroll
    for (int i = 0; i < NI; i++) {
        int j = lane + 32 * i;
        hsel[i] = (H == 1) ? 0 : ((j < M) ? (j / O) : 0);
    }
    float acc[NI];
#pragma unroll
    for (int i = 0; i < NI; i++) {
        int j = lane + 32 * i;
        if (j < M) {
            float ws = (H == 1) ? wse0 : (hsel[i] == 0 ? wse0 : (hsel[i] == 1 ? wse1 : wse2));
            acc[i] = ws * __ldg(&hn[j]);
        } else acc[i] = 0.f;
    }
    // pass 2: software-pipelined — s0 = col for edge e (resolved last iter),
    // s1 = col for e+1, eq0 = es/ed for edge e (issued last iter).
    int e = beg;
    int s0 = 0, s1 = 0;
    float4 eq0 = make_float4(0.f, 0.f, 0.f, 0.f);
    if (e < end) s0 = __ldg(&g_col[e]);
    if (e + 1 < end) s1 = __ldg(&g_col[e + 1]);
    if (e < end) eq0 = __ldg((const float4*)(g_h + (size_t)s0 * SIN + ESOFF));
    while (e < end) {
        int s = s0;
        float4 eq = eq0;
        // prefetch next iteration's operands before any dependent math
        if (e + 1 < end) eq0 = __ldg((const float4*)(g_h + (size_t)s1 * SIN + ESOFF));
        s0 = s1;
        if (e + 2 < end) s1 = __ldg(&g_col[e + 2]);
        float w0 = __expf(leakyf(eq.x + edv0) - mx0); z0 += w0;
        float w1 = w0, w2 = w0;
        if (H > 1) { w1 = __expf(leakyf(eq.y + edv1) - mx1); z1 += w1; }
        if (H > 2) { w2 = __expf(leakyf(eq.z + edv2) - mx2); z2 += w2; }
        const float* hs = g_h + (size_t)s * SIN;
#pragma unroll
        for (int i = 0; i < NI; i++) {
            int j = lane + 32 * i;
            if (j < M) {
                float ws = (H == 1) ? w0 : (hsel[i] == 0 ? w0 : (hsel[i] == 1 ? w1 : w2));
                acc[i] += ws * __ldg(&hs[j]);
            }
        }
        e++;
    }
#pragma unroll
    for (int i = 0; i < NI; i++) {
        int j = lane + 32 * i;
        if (j < M) {
            float zz = (H == 1) ? z0 : (hsel[i] == 0 ? z0 : (hsel[i] == 1 ? z1 : z2));
            float v = acc[i] / (zz + 1e-16f) + __ldg(&bias[j]);
            if (ACT) v = leakyf(v);
            g_act[(size_t)n * SOUT + j] = v;
        }
    }
}

// ---------------- global mean pool over graphs (vector atomics) ----------------
__global__ void pool_kernel(const int* __restrict__ batch) {
    int gw = (blockIdx.x * blockDim.x + threadIdx.x) >> 5;
    int lane = threadIdx.x & 31;
    if (gw >= NNODES) return;
    int b = __ldg(&batch[gw]);
    float4 v = __ldg((const float4*)(g_act + (size_t)gw * 128) + lane);
    atomicAdd(reinterpret_cast<float4*>(g_pool + b * 128) + lane, v);
    if (lane == 0) atomicAdd(&g_cnt[b], 1);
}

__global__ void finalize_kernel(float* __restrict__ out) {
    int b = blockIdx.x, j = threadIdx.x;
    int c = g_cnt[b];
    float cf = (float)(c > 1 ? c : 1);
    out[b * 256 + j] = g_pool[b * 128 + j] / cf;
}

// ---------------- location encoder MLP + mean over locations ----------------
__global__ void locmlp_kernel(const float* __restrict__ loc, const float* __restrict__ Wl1,
                              const float* __restrict__ bl1, const float* __restrict__ Wl2,
                              const float* __restrict__ bl2, float* __restrict__ out) {
    int b = blockIdx.x;
    int t = threadIdx.x;  // 256
    __shared__ float hid[256];
    float w1a = __ldg(&Wl1[t]), w1b = __ldg(&Wl1[256 + t]), b1v = __ldg(&bl1[t]);
    float accv = 0.f;
    for (int l = 0; l < NLOCS; l++) {
        float lx = __ldg(&loc[(b * NLOCS + l) * 2 + 0]);
        float ly = __ldg(&loc[(b * NLOCS + l) * 2 + 1]);
        float hv = tanhf(lx * w1a + ly * w1b + b1v);
        __syncthreads();
        hid[t] = hv;
        __syncthreads();
        if (t < 128) {
            float s = 0.f;
#pragma unroll 8
            for (int k = 0; k < 256; k++) s += hid[k] * __ldg(&Wl2[k * 128 + t]);
            accv += s;
        }
    }
    if (t < 128) out[b * 256 + 128 + t] = accv / (float)NLOCS + __ldg(&bl2[t]);
}

// ---------------- launch ----------------
extern "C" void kernel_launch(void* const* d_in, const int* in_sizes, int n_in,
                              void* d_out, int out_size) {
    const float* x   = (const float*)d_in[0];
    const float* loc = (const float*)d_in[1];
    const int* ei    = (const int*)d_in[2];
    const int* batch = (const int*)d_in[3];
    const float* W0  = (const float*)d_in[4];
    const float* as0 = (const float*)d_in[5];
    const float* ad0 = (const float*)d_in[6];
    const float* b0  = (const float*)d_in[7];
    const float* W1  = (const float*)d_in[8];
    const float* as1 = (const float*)d_in[9];
    const float* ad1 = (const float*)d_in[10];
    const float* b1  = (const float*)d_in[11];
    const float* W2  = (const float*)d_in[12];
    const float* as2 = (const float*)d_in[13];
    const float* ad2 = (const float*)d_in[14];
    const float* b2  = (const float*)d_in[15];
    const float* Wl1 = (const float*)d_in[16];
    const float* bl1 = (const float*)d_in[17];
    const float* Wl2 = (const float*)d_in[18];
    const float* bl2 = (const float*)d_in[19];
    float* out = (float*)d_out;
    const int* srcv = ei;
    const int* dstv = ei + NEDGES;

    int gatherBlocks = (NNODES + 7) / 8;
    int gemmBlocks = (NNODES + 63) / 64;
    int nscan = (NNODES + 1023) / 1024;  // 49

    // launch order chosen so ncu (-s 5 -c 1) captures gather_kernel L0 at index 5
    setup_kernel<<<345, 256>>>(W0, as0, ad0, W1, as1, ad1, W2, as2, ad2);          // 0
    hist_kernel<<<(NEDGES + 255) / 256, 256>>>(dstv);                              // 1
    scan_lookback<<<nscan, 1024>>>();                                              // 2
    fill_kernel<<<(NEDGES + 255) / 256, 256>>>(srcv, dstv);                        // 3
    gemm0_kernel<<<NNODES, 160>>>(x);                                              // 4
    gather_kernel<3, 43, 129, 144, 132, 136, 132, 1><<<gatherBlocks, 256>>>(b0);   // 5 <- profiled
    gemm_tiled<144><<<gemmBlocks, dim3(36, 8)>>>(1, NNODES);                       // 6
    gather_kernel<3, 43, 129, 144, 132, 136, 132, 1><<<gatherBlocks, 256>>>(b1);   // 7
    gemm_tiled<132><<<gemmBlocks, dim3(33, 8)>>>(2, NNODES);                       // 8
    gather_kernel<1, 128, 128, 132, 128, 129, 128, 0><<<gatherBlocks, 256>>>(b2);  // 9
    pool_kernel<<<gatherBlocks, 256>>>(batch);                                     // 10
    finalize_kernel<<<64, 128>>>(out);                                             // 11
    locmlp_kernel<<<64, 256>>>(loc, Wl1, bl1, Wl2, bl2, out);                      // 12
}

// round 9
// speedup vs baseline: 1.7778x; 1.7778x over previous
#include <cuda_runtime.h>
#include <math.h>

#define NNODES 50000
#define NEDGES 800000
#define NGRAPHS 64
#define NLOCS 50

// ---------------- device scratch ----------------
__device__ float g_h[(size_t)NNODES * 144];    // GEMM out (features + es + ed)
__device__ float g_act[(size_t)NNODES * 132];  // gather out / next GEMM in
__device__ float g_Wp0[8 * 144];
__device__ float g_Wp1[132 * 144];
__device__ float g_Wp2[132 * 132];
__device__ int g_deg[NNODES];
__device__ int g_cur[NNODES];
__device__ int g_rowptr[NNODES + 1];
__device__ int g_col[NEDGES];
__device__ int g_bsum[64];
__device__ int g_boff[64];
__device__ float g_pool[NGRAPHS * 128];
__device__ int g_cnt[NGRAPHS];

__device__ __forceinline__ float leakyf(float v) { return v > 0.f ? v : 0.2f * v; }

// ---- f32x2 packed math (Blackwell FFMA2) ----
__device__ __forceinline__ unsigned long long ffma2(unsigned long long a, unsigned long long b,
                                                    unsigned long long c) {
    unsigned long long d;
    asm("fma.rn.f32x2 %0, %1, %2, %3;" : "=l"(d) : "l"(a), "l"(b), "l"(c));
    return d;
}
__device__ __forceinline__ unsigned long long dupf2(float x) {
    unsigned long long d;
    asm("mov.b64 %0, {%1, %1};" : "=l"(d) : "f"(x));
    return d;
}
__device__ __forceinline__ void unpackf2(unsigned long long v, float& lo, float& hi) {
    asm("mov.b64 {%0, %1}, %2;" : "=f"(lo), "=f"(hi) : "l"(v));
}

// ---------------- weight packing (fold attention dots into GEMM) ----------------
__global__ void pack_weights(const float* __restrict__ W, const float* __restrict__ avs,
                             const float* __restrict__ avd, int which,
                             int K, int M, int MP, int KP, int H, int O, int ES, int ED) {
    float* Wp = (which == 0) ? g_Wp0 : (which == 1) ? g_Wp1 : g_Wp2;
    int i = blockIdx.x * blockDim.x + threadIdx.x;
    if (i >= KP * MP) return;
    int k = i / MP, j = i % MP;
    float v = 0.f;
    if (k < K) {
        if (j < M) {
            v = W[k * M + j];
        } else if (j >= ES && j < ES + H) {
            int h = j - ES; float s = 0.f;
            for (int o = 0; o < O; o++) s += W[k * M + h * O + o] * avs[h * O + o];
            v = s;
        } else if (j >= ED && j < ED + H) {
            int h = j - ED; float s = 0.f;
            for (int o = 0; o < O; o++) s += W[k * M + h * O + o] * avd[h * O + o];
            v = s;
        }
    }
    Wp[i] = v;
}

// ---------------- CSR build ----------------
__global__ void zero_aux() {
    int i = blockIdx.x * blockDim.x + threadIdx.x;
    if (i < NNODES) { g_deg[i] = 0; g_cur[i] = 0; }
    if (i < NGRAPHS * 128) g_pool[i] = 0.f;
    if (i < NGRAPHS) g_cnt[i] = 0;
}

__global__ void hist_kernel(const int* __restrict__ dstv) {
    int i = blockIdx.x * blockDim.x + threadIdx.x;
    if (i < NEDGES) atomicAdd(&g_deg[dstv[i]], 1);
}

// 3-kernel parallel exclusive scan of degrees -> rowptr
__global__ void scan_blocks() {
    __shared__ int buf[1024];
    int t = threadIdx.x;
    int idx = blockIdx.x * 1024 + t;
    int v = (idx < NNODES) ? g_deg[idx] : 0;
    buf[t] = v;
    __syncthreads();
    for (int off = 1; off < 1024; off <<= 1) {
        int a = (t >= off) ? buf[t - off] : 0;
        __syncthreads();
        buf[t] += a;
        __syncthreads();
    }
    if (idx < NNODES) g_rowptr[idx + 1] = buf[t];
    if (t == 1023) g_bsum[blockIdx.x] = buf[1023];
}

__global__ void scan_tops(int nblk) {
    __shared__ int buf[64];
    int t = threadIdx.x;
    int v = (t < nblk) ? g_bsum[t] : 0;
    buf[t] = v;
    __syncthreads();
    for (int off = 1; off < 64; off <<= 1) {
        int a = (t >= off) ? buf[t - off] : 0;
        __syncthreads();
        buf[t] += a;
        __syncthreads();
    }
    if (t < nblk) g_boff[t] = buf[t] - v;  // exclusive
}

__global__ void scan_add() {
    int t = threadIdx.x;
    int idx = blockIdx.x * 1024 + t;
    if (idx < NNODES) g_rowptr[idx + 1] += g_boff[blockIdx.x];
    if (idx == 0) g_rowptr[0] = 0;
}

__global__ void fill_kernel(const int* __restrict__ srcv, const int* __restrict__ dstv) {
    int i = blockIdx.x * blockDim.x + threadIdx.x;
    if (i < NEDGES) {
        int d = dstv[i];
        int p = atomicAdd(&g_cur[d], 1);
        g_col[g_rowptr[d] + p] = srcv[i];
    }
}

// ---------------- layer-0 GEMM (K=6) ----------------
__global__ void gemm0_kernel(const float* __restrict__ x) {
    int n = blockIdx.x;
    int j = threadIdx.x;
    float xr[6];
#pragma unroll
    for (int k = 0; k < 6; k++) xr[k] = __ldg(&x[n * 6 + k]);
    if (j < 144) {
        float a = 0.f;
#pragma unroll
        for (int k = 0; k < 6; k++) a += xr[k] * g_Wp0[k * 144 + j];
        g_h[(size_t)n * 144 + j] = a;
    }
}

// ---------------- tiled GEMM with f32x2: g_act[N,132] @ Wp[132,MP] -> g_h[N,MP] ----------------
template <int MP>
__global__ void gemm_tiled(int wsel, int N) {
    constexpr int KP = 132;
    constexpr int TXN = MP / 4;
    constexpr int NTH = TXN * 8;
    __shared__ float xs[KP][68];  // transposed A tile, row stride 272B
    const float* Wp = (wsel == 1) ? g_Wp1 : g_Wp2;
    const float4* W4 = (const float4*)Wp;
    int tx = threadIdx.x, ty = threadIdx.y;
    int t = ty * TXN + tx;
    int n0 = blockIdx.x * 64;
    for (int i = t; i < 64 * 33; i += NTH) {
        int n = i / 33, k4 = i % 33;
        int gn = n0 + n;
        float4 v = make_float4(0.f, 0.f, 0.f, 0.f);
        if (gn < N) v = __ldg((const float4*)(g_act + (size_t)gn * 132 + k4 * 4));
        xs[k4 * 4 + 0][n] = v.x;
        xs[k4 * 4 + 1][n] = v.y;
        xs[k4 * 4 + 2][n] = v.z;
        xs[k4 * 4 + 3][n] = v.w;
    }
    __syncthreads();
    unsigned long long acc2[4][4];  // [node-pair][col]
#pragma unroll
    for (int p = 0; p < 4; p++)
#pragma unroll
        for (int c = 0; c < 4; c++) acc2[p][c] = 0ull;
    int nb = ty * 8;
#pragma unroll 2
    for (int k = 0; k < KP; k++) {
        float4 w = __ldg(&W4[k * TXN + tx]);
        unsigned long long wd0 = dupf2(w.x), wd1 = dupf2(w.y), wd2 = dupf2(w.z), wd3 = dupf2(w.w);
        const unsigned long long* xr = (const unsigned long long*)&xs[k][nb];
        unsigned long long x0 = xr[0], x1 = xr[1], x2 = xr[2], x3 = xr[3];
        acc2[0][0] = ffma2(x0, wd0, acc2[0][0]);
        acc2[0][1] = ffma2(x0, wd1, acc2[0][1]);
        acc2[0][2] = ffma2(x0, wd2, acc2[0][2]);
        acc2[0][3] = ffma2(x0, wd3, acc2[0][3]);
        acc2[1][0] = ffma2(x1, wd0, acc2[1][0]);
        acc2[1][1] = ffma2(x1, wd1, acc2[1][1]);
        acc2[1][2] = ffma2(x1, wd2, acc2[1][2]);
        acc2[1][3] = ffma2(x1, wd3, acc2[1][3]);
        acc2[2][0] = ffma2(x2, wd0, acc2[2][0]);
        acc2[2][1] = ffma2(x2, wd1, acc2[2][1]);
        acc2[2][2] = ffma2(x2, wd2, acc2[2][2]);
        acc2[2][3] = ffma2(x2, wd3, acc2[2][3]);
        acc2[3][0] = ffma2(x3, wd0, acc2[3][0]);
        acc2[3][1] = ffma2(x3, wd1, acc2[3][1]);
        acc2[3][2] = ffma2(x3, wd2, acc2[3][2]);
        acc2[3][3] = ffma2(x3, wd3, acc2[3][3]);
    }
#pragma unroll
    for (int p = 0; p < 4; p++) {
        float lo0, hi0, lo1, hi1, lo2, hi2, lo3, hi3;
        unpackf2(acc2[p][0], lo0, hi0);
        unpackf2(acc2[p][1], lo1, hi1);
        unpackf2(acc2[p][2], lo2, hi2);
        unpackf2(acc2[p][3], lo3, hi3);
        int gnl = n0 + nb + 2 * p;
        int gnh = gnl + 1;
        if (gnl < N) {
            float4 o = make_float4(lo0, lo1, lo2, lo3);
            *(float4*)(g_h + (size_t)gnl * MP + tx * 4) = o;
        }
        if (gnh < N) {
            float4 o = make_float4(hi0, hi1, hi2, hi3);
            *(float4*)(g_h + (size_t)gnh * MP + tx * 4) = o;
        }
    }
}

// ---------------- GAT gather (R1 structure): warp per dst node, CSR in-edges + self-loop ----------------
template <int H, int O, int M, int SIN, int ESOFF, int EDOFF, int SOUT, int ACT, int FUSEPOOL>
__global__ void gather_kernel(const float* __restrict__ bias, const int* __restrict__ batch) {
    int gw = (blockIdx.x * blockDim.x + threadIdx.x) >> 5;
    int lane = threadIdx.x & 31;
    int wid = threadIdx.x >> 5;
    __shared__ float sh[8][128];
    if (gw >= NNODES) return;
    int n = gw;
    const float* hn = g_h + (size_t)n * SIN;
    float edv[3], esn[3], selfe[3], mx[3];
#pragma unroll
    for (int h = 0; h < H; h++) {
        edv[h] = __ldg(&hn[EDOFF + h]);
        esn[h] = __ldg(&hn[ESOFF + h]);
        selfe[h] = leakyf(esn[h] + edv[h]);
        mx[h] = selfe[h];
    }
    int beg = __ldg(&g_rowptr[n]);
    int end = __ldg(&g_rowptr[n + 1]);
    // pass 1: max over in-edges (lanes parallel over edges)
    for (int e = beg + lane; e < end; e += 32) {
        int s = __ldg(&g_col[e]);
        float4 eq = __ldg((const float4*)(g_h + (size_t)s * SIN + ESOFF));
        mx[0] = fmaxf(mx[0], leakyf(eq.x + edv[0]));
        if (H > 1) mx[1] = fmaxf(mx[1], leakyf(eq.y + edv[1]));
        if (H > 2) mx[2] = fmaxf(mx[2], leakyf(eq.z + edv[2]));
    }
#pragma unroll
    for (int h = 0; h < H; h++)
#pragma unroll
        for (int o = 16; o > 0; o >>= 1) mx[h] = fmaxf(mx[h], __shfl_xor_sync(0xffffffffu, mx[h], o));
    // pass 2: accumulate (edges sequential, lanes over features)
    constexpr int NI = (M + 31) / 32;
    float z[3] = {0.f, 0.f, 0.f};
    float w0s, w1s = 0.f, w2s = 0.f;
    w0s = __expf(selfe[0] - mx[0]); z[0] = w0s;
    if (H > 1) { w1s = __expf(selfe[1] - mx[1]); z[1] = w1s; }
    if (H > 2) { w2s = __expf(selfe[2] - mx[2]); z[2] = w2s; }
    float acc[NI];
#pragma unroll
    for (int i = 0; i < NI; i++) {
        int j = lane + 32 * i;
        if (j < M) {
            int hdi = j / O;
            float ws = (H == 1) ? w0s : (hdi == 0 ? w0s : (hdi == 1 ? w1s : w2s));
            acc[i] = ws * __ldg(&hn[j]);
        } else acc[i] = 0.f;
    }
    int e = beg;
    int s_next = (e < end) ? __ldg(&g_col[e]) : 0;
    while (e < end) {
        int s = s_next;
        if (e + 1 < end) s_next = __ldg(&g_col[e + 1]);
        const float* hs = g_h + (size_t)s * SIN;
        float4 eq = __ldg((const float4*)(hs + ESOFF));
        float w0 = __expf(leakyf(eq.x + edv[0]) - mx[0]); z[0] += w0;
        float w1 = w0, w2 = w0;
        if (H > 1) { w1 = __expf(leakyf(eq.y + edv[1]) - mx[1]); z[1] += w1; }
        if (H > 2) { w2 = __expf(leakyf(eq.z + edv[2]) - mx[2]); z[2] += w2; }
#pragma unroll
        for (int i = 0; i < NI; i++) {
            int j = lane + 32 * i;
            if (j < M) {
                int hdi = j / O;
                float ws = (H == 1) ? w0 : (hdi == 0 ? w0 : (hdi == 1 ? w1 : w2));
                acc[i] += ws * __ldg(&hs[j]);
            }
        }
        e++;
    }
    if (!FUSEPOOL) {
#pragma unroll
        for (int i = 0; i < NI; i++) {
            int j = lane + 32 * i;
            if (j < M) {
                int hdi = j / O;
                float zz = (H == 1) ? z[0] : (hdi == 0 ? z[0] : (hdi == 1 ? z[1] : z[2]));
                float v = acc[i] / (zz + 1e-16f) + __ldg(&bias[j]);
                if (ACT) v = leakyf(v);
                g_act[(size_t)n * SOUT + j] = v;
            }
        }
    } else {
        // layer 2 (H==1, M==128): stage in shared, transpose to float4, vector-atomic into pool
        int b = __ldg(&batch[n]);
#pragma unroll
        for (int i = 0; i < NI; i++) {
            int j = lane + 32 * i;
            if (j < M) {
                float v = acc[i] / (z[0] + 1e-16f) + __ldg(&bias[j]);
                sh[wid][j] = v;
            }
        }
        __syncwarp();
        float4 vv = *(float4*)&sh[wid][lane * 4];
        atomicAdd(reinterpret_cast<float4*>(g_pool + b * 128) + lane, vv);
        if (lane == 0) atomicAdd(&g_cnt[b], 1);
    }
}

__global__ void finalize_kernel(float* __restrict__ out) {
    int b = blockIdx.x, j = threadIdx.x;  // 256 threads
    if (j < 128) {
        int c = g_cnt[b];
        float cf = (float)(c > 1 ? c : 1);
        out[b * 256 + j] = g_pool[b * 128 + j] / cf;
    } else {
        out[b * 256 + j] = 0.f;  // zero loc half for atomic accumulation
    }
}

// ---------------- location MLP: 4 blocks per graph, atomic accumulate ----------------
__global__ void locmlp_kernel(const float* __restrict__ loc, const float* __restrict__ Wl1,
                              const float* __restrict__ bl1, const float* __restrict__ Wl2,
                              const float* __restrict__ bl2, float* __restrict__ out) {
    int b = blockIdx.x >> 2;
    int part = blockIdx.x & 3;
    int t = threadIdx.x;  // 256
    int lbeg = part * 12 + min(part, 2);
    int lend = (part + 1) * 12 + min(part + 1, 2);
    __shared__ float hid[256];
    float w1a = __ldg(&Wl1[t]), w1b = __ldg(&Wl1[256 + t]), b1v = __ldg(&bl1[t]);
    float accv = 0.f;
    for (int l = lbeg; l < lend; l++) {
        float lx = __ldg(&loc[(b * NLOCS + l) * 2 + 0]);
        float ly = __ldg(&loc[(b * NLOCS + l) * 2 + 1]);
        float hv = tanhf(lx * w1a + ly * w1b + b1v);
        __syncthreads();
        hid[t] = hv;
        __syncthreads();
        if (t < 128) {
            float s = 0.f;
#pragma unroll 8
            for (int k = 0; k < 256; k++) s += hid[k] * __ldg(&Wl2[k * 128 + t]);
            accv += s;
        }
    }
    if (t < 128) {
        float v = accv * (1.f / (float)NLOCS);
        if (part == 0) v += __ldg(&bl2[t]);
        atomicAdd(&out[b * 256 + 128 + t], v);
    }
}

// ---------------- launch ----------------
extern "C" void kernel_launch(void* const* d_in, const int* in_sizes, int n_in,
                              void* d_out, int out_size) {
    const float* x   = (const float*)d_in[0];
    const float* loc = (const float*)d_in[1];
    const int* ei    = (const int*)d_in[2];
    const int* batch = (const int*)d_in[3];
    const float* W0  = (const float*)d_in[4];
    const float* as0 = (const float*)d_in[5];
    const float* ad0 = (const float*)d_in[6];
    const float* b0  = (const float*)d_in[7];
    const float* W1  = (const float*)d_in[8];
    const float* as1 = (const float*)d_in[9];
    const float* ad1 = (const float*)d_in[10];
    const float* b1  = (const float*)d_in[11];
    const float* W2  = (const float*)d_in[12];
    const float* as2 = (const float*)d_in[13];
    const float* ad2 = (const float*)d_in[14];
    const float* b2  = (const float*)d_in[15];
    const float* Wl1 = (const float*)d_in[16];
    const float* bl1 = (const float*)d_in[17];
    const float* Wl2 = (const float*)d_in[18];
    const float* bl2 = (const float*)d_in[19];
    float* out = (float*)d_out;
    const int* srcv = ei;
    const int* dstv = ei + NEDGES;

    pack_weights<<<(8 * 144 + 255) / 256, 256>>>(W0, as0, ad0, 0, 6, 129, 144, 8, 3, 43, 132, 136);
    pack_weights<<<(132 * 144 + 255) / 256, 256>>>(W1, as1, ad1, 1, 129, 129, 144, 132, 3, 43, 132, 136);
    pack_weights<<<(132 * 132 + 255) / 256, 256>>>(W2, as2, ad2, 2, 129, 128, 132, 132, 1, 128, 128, 129);

    int nscan = (NNODES + 1023) / 1024;  // 49
    zero_aux<<<(NNODES + 255) / 256, 256>>>();
    hist_kernel<<<(NEDGES + 255) / 256, 256>>>(dstv);
    scan_blocks<<<nscan, 1024>>>();
    scan_tops<<<1, 64>>>(nscan);
    scan_add<<<nscan, 1024>>>();
    fill_kernel<<<(NEDGES + 255) / 256, 256>>>(srcv, dstv);

    int gatherBlocks = (NNODES + 7) / 8;
    int gemmBlocks = (NNODES + 63) / 64;

    gemm0_kernel<<<NNODES, 160>>>(x);
    gather_kernel<3, 43, 129, 144, 132, 136, 132, 1, 0><<<gatherBlocks, 256>>>(b0, batch);
    gemm_tiled<144><<<gemmBlocks, dim3(36, 8)>>>(1, NNODES);
    gather_kernel<3, 43, 129, 144, 132, 136, 132, 1, 0><<<gatherBlocks, 256>>>(b1, batch);
    gemm_tiled<132><<<gemmBlocks, dim3(33, 8)>>>(2, NNODES);
    gather_kernel<1, 128, 128, 132, 128, 129, 128, 0, 1><<<gatherBlocks, 256>>>(b2, batch);

    finalize_kernel<<<64, 256>>>(out);
    locmlp_kernel<<<256, 256>>>(loc, Wl1, bl1, Wl2, bl2, out);
}